// round 8
// baseline (speedup 1.0000x reference)
#include <cuda_runtime.h>
#include <cuda_bf16.h>
#include <math.h>

// Problem constants
#define BATCH 256
#define Hh 26
#define Ww 26
#define HW (Hh * Ww)          // 676
#define A_NUM 5
#define NCLS 20
#define CPA 25                 // channels per anchor (20 cls, conf, xy, wh)
#define CH (A_NUM * CPA)       // 125
#define TOTAL (BATCH * HW)     // 173056
#define TPB 128
#define WORKB 676              // 128*2*676 == TOTAL exactly
#define NBLOCKS 740            // padded: 5 per SM balanced wave

__device__ __constant__ float c_aw[5] = {1.3221f, 3.19275f, 5.05587f, 9.47112f, 11.2364f};
__device__ __constant__ float c_ah[5] = {1.73145f, 4.00944f, 8.09892f, 4.84053f, 10.0071f};

__device__ __forceinline__ float fsigmoid(float x) {
    return __fdividef(1.0f, 1.0f + __expf(-x));
}

__global__ void __launch_bounds__(TPB, 5) yolo_loss_kernel(
    const float* __restrict__ pred,   // (B, 125, 26, 26)
    const float* __restrict__ tgt,    // (B, 26, 26, 25)
    float* __restrict__ out)          // 4 floats: box, conf, noobj, cls
{
    float box_l = 0.f, conf_l = 0.f, noobj_l = 0.f, cls_l = 0.f;

    int i2 = (blockIdx.x * TPB + threadIdx.x) * 2;   // even cell index

    if (i2 < TOTAL) {
        int b = i2 / HW;
        int hw = i2 - b * HW;                        // even; hw+1 same row
        const float* __restrict__ pbase = pred + (size_t)b * CH * HW + hw;

        // ---- front-batch pred loads: 25 LDG.64, each covers BOTH cells
        float2 p[A_NUM * 5];
        #pragma unroll
        for (int a = 0; a < A_NUM; a++) {
            #pragma unroll
            for (int j = 0; j < 5; j++) {
                p[a * 5 + j] = __ldg((const float2*)&pbase[(a * CPA + 20 + j) * HW]);
            }
        }

        // ---- targets for both cells
        const float* __restrict__ t0 = tgt + (size_t)i2 * CPA;
        const float* __restrict__ t1 = t0 + CPA;
        // t0[20..23] 8B-aligned (i2*25+20 even)
        float2 t0a = __ldg((const float2*)&t0[20]);   // conf0, x0
        float2 t0b = __ldg((const float2*)&t0[22]);   // y0, w0
        float  gh0 = __ldg(&t0[24]);
        float gconf1 = __ldg(&t1[20]);
        float gx1v = __ldg(&t1[21]), gy1v = __ldg(&t1[22]);
        float gw1v = __ldg(&t1[23]), gh1v = __ldg(&t1[24]);

        float gconf_c[2] = {t0a.x, gconf1};
        float gx_c[2] = {t0a.y, gx1v};
        float gy_c[2] = {t0b.x, gy1v};
        float gw_c[2] = {t0b.y, gw1v};
        float gh_c[2] = {gh0,  gh1v};

        #pragma unroll
        for (int c = 0; c < 2; c++) {
            float gx = gx_c[c], gy = gy_c[c], gw = gw_c[c], gh = gh_c[c];
            float gconf = gconf_c[c];

            float gx1 = gx - 0.5f * gw, gy1 = gy - 0.5f * gh;
            float gx2 = gx + 0.5f * gw, gy2 = gy + 0.5f * gh;
            float garea = gw * gh;

            float best_iou = -1.0f;
            int   best_a   = 0;
            float bpx = 0.f, bpy = 0.f, bpw = 0.f, bph = 0.f;
            float btc = 0.f;

            #pragma unroll
            for (int a = 0; a < A_NUM; a++) {
                float tc = c ? p[a * 5 + 0].y : p[a * 5 + 0].x;
                float vx = c ? p[a * 5 + 1].y : p[a * 5 + 1].x;
                float vy = c ? p[a * 5 + 2].y : p[a * 5 + 2].x;
                float vw = c ? p[a * 5 + 3].y : p[a * 5 + 3].x;
                float vh = c ? p[a * 5 + 4].y : p[a * 5 + 4].x;

                float px = fsigmoid(vx);
                float py = fsigmoid(vy);
                float pw = __expf(vw) * c_aw[a];
                float ph = __expf(vh) * c_ah[a];

                float ax1 = px - 0.5f * pw, ay1 = py - 0.5f * ph;
                float ax2 = px + 0.5f * pw, ay2 = py + 0.5f * ph;
                float iw = fmaxf(fminf(ax2, gx2) - fmaxf(ax1, gx1), 0.0f);
                float ih = fmaxf(fminf(ay2, gy2) - fmaxf(ay1, gy1), 0.0f);
                float inter = iw * ih;
                float uni = pw * ph + garea - inter;
                float iou = __fdividef(inter, uni + 1e-10f);

                if (iou > best_iou) {           // first-max argmax (strict >)
                    best_iou = iou;
                    best_a = a;
                    bpx = px; bpy = py; bpw = pw; bph = ph; btc = tc;
                }
            }

            float bconf = fsigmoid(btc);

            bool obj = (gconf != 0.0f);
            if (obj) {
                float dx = bpx - gx, dy = bpy - gy, dw = bpw - gw, dh = bph - gh;
                box_l  += dx * dx + dy * dy + dw * dw + dh * dh;
                float dc = bconf - gconf;
                conf_l += dc * dc;

                // class loss: gather 20 logits of best anchor for THIS cell
                const float* __restrict__ lb = pbase + (size_t)(best_a * CPA) * HW + c;
                const float* __restrict__ tt = c ? t1 : t0;
                float logits[NCLS];
                float m = -INFINITY;
                #pragma unroll
                for (int k = 0; k < NCLS; k++) {
                    float v = __ldg(&lb[k * HW]);
                    logits[k] = v;
                    m = fmaxf(m, v);
                }
                float s = 0.f;
                #pragma unroll
                for (int k = 0; k < NCLS; k++) s += __expf(logits[k] - m);
                float lse = m + __logf(s);

                int label = 0;
                float bestv = __ldg(&tt[0]);
                #pragma unroll
                for (int k = 1; k < NCLS; k++) {
                    float v = __ldg(&tt[k]);
                    if (v > bestv) { bestv = v; label = k; }
                }
                cls_l += lse - logits[label];
            } else {
                noobj_l += bconf * bconf;
            }
        }
    }

    // warp reduce (4 warps per block)
    #pragma unroll
    for (int off = 16; off > 0; off >>= 1) {
        box_l   += __shfl_down_sync(0xFFFFFFFFu, box_l,   off);
        conf_l  += __shfl_down_sync(0xFFFFFFFFu, conf_l,  off);
        noobj_l += __shfl_down_sync(0xFFFFFFFFu, noobj_l, off);
        cls_l   += __shfl_down_sync(0xFFFFFFFFu, cls_l,   off);
    }

    __shared__ float sm[4][4];
    int lane = threadIdx.x & 31;
    int wid  = threadIdx.x >> 5;
    if (lane == 0) {
        sm[0][wid] = box_l;
        sm[1][wid] = conf_l;
        sm[2][wid] = noobj_l;
        sm[3][wid] = cls_l;
    }
    __syncthreads();
    if (wid == 0 && lane == 0) {
        float v0 = sm[0][0] + sm[0][1] + sm[0][2] + sm[0][3];
        float v1 = sm[1][0] + sm[1][1] + sm[1][2] + sm[1][3];
        float v2 = sm[2][0] + sm[2][1] + sm[2][2] + sm[2][3];
        float v3 = sm[3][0] + sm[3][1] + sm[3][2] + sm[3][3];
        const float inv_b = 1.0f / (float)BATCH;
        atomicAdd(out + 0, v0 * (5.0f * inv_b));   // LAMBDA_COORD
        atomicAdd(out + 1, v1 * (1.0f * inv_b));   // LAMBDA_OBJ
        atomicAdd(out + 2, v2 * (0.5f * inv_b));   // LAMBDA_NOOBJ
        atomicAdd(out + 3, v3 * (1.0f * inv_b));   // LAMBDA_CLS
    }
}

extern "C" void kernel_launch(void* const* d_in, const int* in_sizes, int n_in,
                              void* d_out, int out_size) {
    const float* pred = (const float*)d_in[0];
    const float* tgt  = (const float*)d_in[1];
    float* out = (float*)d_out;

    cudaMemsetAsync(out, 0, 4 * sizeof(float), 0);

    yolo_loss_kernel<<<NBLOCKS, TPB>>>(pred, tgt, out);
}